// round 14
// baseline (speedup 1.0000x reference)
#include <cuda_runtime.h>
#include <cuda_fp16.h>
#include <cstdint>

__device__ __forceinline__ float cos_fast(float x) {
    float y;
    asm("cos.approx.ftz.f32 %0, %1;" : "=f"(y) : "f"(x));
    return y;
}
// One MUFU instruction -> two tanhs (sm_75+)
__device__ __forceinline__ __half2 tanh_h2(__half2 x) {
    __half2 y;
    asm("tanh.approx.f16x2 %0, %1;"
        : "=r"(*reinterpret_cast<uint32_t*>(&y))
        : "r"(*reinterpret_cast<const uint32_t*>(&x)));
    return y;
}

#define N_LAYERS 5
#define Q_DEPTH  2

// fp32 coef smem layout:
// [0] wf0'  [1] wf1'  [2] bf' + K0
// [3] K1  [4] K2  [5] K3-K4  [6] K4
// half2 coef smem layout (per layer l):
// [l*3+0] = (w00, w10)   column-0 broadcast weights
// [l*3+1] = (w01, w11)   column-1 broadcast weights
// [l*3+2] = (b0,  b1)    bias pair
#define NF32 7
#define NH2  (N_LAYERS * 3)

__device__ __forceinline__ void build_coefs(
    float* sf, __half2* sh,
    const float* __restrict__ Ws, const float* __restrict__ bs,
    const float* __restrict__ scales, const float* __restrict__ shifts,
    const float* __restrict__ Wf, const float* __restrict__ bf,
    const float* __restrict__ theta)
{
    // ---- fold scale/shift of layer l-1 into layer l (fp32), emit half2 ----
    float W[N_LAYERS][4], B[N_LAYERS][2];
    W[0][0] = Ws[0]; W[0][1] = Ws[1]; W[0][2] = Ws[2]; W[0][3] = Ws[3];
    B[0][0] = bs[0]; B[0][1] = bs[1];
#pragma unroll
    for (int l = 1; l < N_LAYERS; ++l) {
        float sc0 = scales[(l-1)*2+0], sc1 = scales[(l-1)*2+1];
        float sh0 = shifts[(l-1)*2+0], sh1 = shifts[(l-1)*2+1];
        float w00 = Ws[l*4+0], w01 = Ws[l*4+1], w10 = Ws[l*4+2], w11 = Ws[l*4+3];
        W[l][0] = w00 * sc0;
        W[l][1] = w01 * sc1;
        W[l][2] = w10 * sc0;
        W[l][3] = w11 * sc1;
        B[l][0] = fmaf(w00, sh0, fmaf(w01, sh1, bs[l*2+0]));
        B[l][1] = fmaf(w10, sh0, fmaf(w11, sh1, bs[l*2+1]));
    }
#pragma unroll
    for (int l = 0; l < N_LAYERS; ++l) {
        sh[l*3+0] = __floats2half2_rn(W[l][0], W[l][2]);   // (w00, w10)
        sh[l*3+1] = __floats2half2_rn(W[l][1], W[l][3]);   // (w01, w11)
        sh[l*3+2] = __floats2half2_rn(B[l][0], B[l][1]);   // (b0,  b1)
    }
    float lsc0 = scales[(N_LAYERS-1)*2+0], lsc1 = scales[(N_LAYERS-1)*2+1];
    float lsh0 = shifts[(N_LAYERS-1)*2+0], lsh1 = shifts[(N_LAYERS-1)*2+1];
    sf[0] = Wf[0] * lsc0;
    sf[1] = Wf[1] * lsc1;
    float bfp = fmaf(Wf[0], lsh0, fmaf(Wf[1], lsh1, bf[0]));

    // ---- U = prod_d [ CZ * (RY1 (x) RY0) ], real 4x4; rows 0 and 3 ----
    float U[4][4];
#pragma unroll
    for (int i = 0; i < 4; ++i)
#pragma unroll
        for (int j = 0; j < 4; ++j)
            U[i][j] = (i == j) ? 1.0f : 0.0f;

#pragma unroll
    for (int d = 0; d < Q_DEPTH; ++d) {
        float a0 = theta[d*2+0] * 0.5f;
        float a1 = theta[d*2+1] * 0.5f;
        float s0, c0, s1, c1;
        __sincosf(a0, &s0, &c0);
        __sincosf(a1, &s1, &c1);
        float ry0[2][2] = {{c0, -s0}, {s0, c0}};
        float ry1[2][2] = {{c1, -s1}, {s1, c1}};
        float M[4][4];
#pragma unroll
        for (int i = 0; i < 4; ++i)
#pragma unroll
            for (int j = 0; j < 4; ++j) {
                float acc = 0.0f;
#pragma unroll
                for (int k = 0; k < 4; ++k)
                    acc = fmaf(ry1[i>>1][k>>1] * ry0[i&1][k&1], U[k][j], acc);
                M[i][j] = acc;
            }
#pragma unroll
        for (int i = 0; i < 4; ++i)
#pragma unroll
            for (int j = 0; j < 4; ++j)
                U[i][j] = (i == 3) ? -M[i][j] : M[i][j];   // CZ flips |11> row
    }

    // q = K0 + K1 cos x0 + K2 cos x1 + K3 cos x0 cos x1 + K4 sin x0 sin x1
    float a = U[0][0]*U[0][0], b = U[0][1]*U[0][1], c = U[0][2]*U[0][2], dd = U[0][3]*U[0][3];
    float e = U[3][0]*U[3][0], f = U[3][1]*U[3][1], g = U[3][2]*U[3][2], h = U[3][3]*U[3][3];
    float cross0 = 2.0f * (U[0][1]*U[0][2] - U[0][0]*U[0][3]);
    float cross3 = 2.0f * (U[3][1]*U[3][2] - U[3][0]*U[3][3]);
    float K0 = 0.5f * ((a + b + c + dd) - (e + f + g + h));
    float K1 = 0.5f * ((a - b + c - dd) - (e - f + g - h));
    float K2 = 0.5f * ((a + b - c - dd) - (e + f - g - h));
    float K3 = 0.5f * ((a - b - c + dd) - (e - f - g + h));
    float K4 = 0.5f * (cross0 - cross3);
    sf[2] = bfp + K0;
    sf[3] = K1;
    sf[4] = K2;
    sf[5] = K3 - K4;     // coefficient of C0*C1 after product-to-sum
    sf[6] = K4;          // coefficient of cos(x0 - x1)
}

__global__ __launch_bounds__(256, 4)
void fraud_hybrid_fused(
    const float4* __restrict__ x4,    // [N/2] of (x0,x1) pairs
    float4*       __restrict__ out4,  // [N/4]
    const float*  __restrict__ x_raw,
    float*        __restrict__ out_raw,
    const float*  __restrict__ Ws, const float* __restrict__ bs,
    const float*  __restrict__ scales, const float* __restrict__ shifts,
    const float*  __restrict__ Wf, const float* __restrict__ bf,
    const float*  __restrict__ theta,
    int n, int noct)
{
    __shared__ float   sf[NF32 + 1];
    __shared__ __half2 sh[NH2];
    if (threadIdx.x == 0)
        build_coefs(sf, sh, Ws, bs, scales, shifts, Wf, bf, theta);
    __syncthreads();

    // hoist constants to registers
    __half2 wc0[N_LAYERS], wc1[N_LAYERS], bb[N_LAYERS];
#pragma unroll
    for (int l = 0; l < N_LAYERS; ++l) {
        wc0[l] = sh[l*3+0];
        wc1[l] = sh[l*3+1];
        bb[l]  = sh[l*3+2];
    }
    const float wf0 = sf[0], wf1 = sf[1], bfK = sf[2];
    const float K1 = sf[3], K2 = sf[4], K34 = sf[5], K4 = sf[6];

    // quantum head: 3 cos (MUFU) + 5 FMA, all fp32
    auto qhead = [&](float x0, float x1) -> float {
        float C0 = cos_fast(x0);
        float C1 = cos_fast(x1);
        float CD = cos_fast(x0 - x1);       // sin x0 sin x1 = CD - C0*C1
        float cc = C0 * C1;
        return fmaf(K1, C0, fmaf(K2, C1, fmaf(K34, cc, K4 * CD)));
    };

    // backbone: fully fp16 — per layer 2 HFMA2 (both channels/instr, lane
    // broadcast folded into .H0_H0/.H1_H1 selectors) + 1 tanh.approx.f16x2.
    // No pack/unpack inside the loop; one cvt in, two out.
    auto backbone = [&](float x0, float x1) -> float {
        __half2 h = __floats2half2_rn(x0, x1);
#pragma unroll
        for (int l = 0; l < N_LAYERS; ++l) {
            __half2 hlo = __low2half2(h);    // (h0, h0)
            __half2 hhi = __high2half2(h);   // (h1, h1)
            __half2 z = __hfma2(hlo, wc0[l], __hfma2(hhi, wc1[l], bb[l]));
            h = tanh_h2(z);
        }
        float2 t = __half22float2(h);
        return fmaf(wf0, t.x, fmaf(wf1, t.y, bfK));
    };

    const int tid = blockIdx.x * blockDim.x + threadIdx.x;

    if (tid < noct) {
        const int i = tid;
        float4 a = __ldg(&x4[4*i+0]);
        float4 b = __ldg(&x4[4*i+1]);
        float4 c = __ldg(&x4[4*i+2]);
        float4 d = __ldg(&x4[4*i+3]);

        float q0 = qhead(a.x, a.y), q1 = qhead(a.z, a.w);
        float q2 = qhead(b.x, b.y), q3 = qhead(b.z, b.w);
        float q4 = qhead(c.x, c.y), q5 = qhead(c.z, c.w);
        float q6 = qhead(d.x, d.y), q7 = qhead(d.z, d.w);

        float r0 = backbone(a.x, a.y) + q0;
        float r1 = backbone(a.z, a.w) + q1;
        float r2 = backbone(b.x, b.y) + q2;
        float r3 = backbone(b.z, b.w) + q3;
        float r4 = backbone(c.x, c.y) + q4;
        float r5 = backbone(c.z, c.w) + q5;
        float r6 = backbone(d.x, d.y) + q6;
        float r7 = backbone(d.z, d.w) + q7;

        out4[2*i+0] = make_float4(r0, r1, r2, r3);
        out4[2*i+1] = make_float4(r4, r5, r6, r7);
    }

    // tail (n not multiple of 8) — defensive; N = 4M is divisible
    int base = noct * 8;
    int rem = n - base;
    if (tid < rem) {
        int idx = base + tid;
        float x0 = x_raw[2*idx], x1 = x_raw[2*idx+1];
        out_raw[idx] = backbone(x0, x1) + qhead(x0, x1);
    }
}

extern "C" void kernel_launch(void* const* d_in, const int* in_sizes, int n_in,
                              void* d_out, int out_size) {
    const float* x      = (const float*)d_in[0];  // [N,2]
    const float* Ws     = (const float*)d_in[1];  // [5,2,2]
    const float* bs     = (const float*)d_in[2];  // [5,2]
    const float* scales = (const float*)d_in[3];  // [5,2]
    const float* shifts = (const float*)d_in[4];  // [5,2]
    const float* Wf     = (const float*)d_in[5];  // [1,2]
    const float* bf     = (const float*)d_in[6];  // [1]
    const float* theta  = (const float*)d_in[7];  // [2,2]

    const int n = out_size;
    const int noct = n >> 3;              // 8 elements per thread, one pass

    const int threads = 256;
    int blocks = (noct + threads - 1) / threads;   // exact: 2048 at N=4M
    if (blocks < 1) blocks = 1;

    fraud_hybrid_fused<<<blocks, threads>>>(
        (const float4*)x, (float4*)d_out, x, (float*)d_out,
        Ws, bs, scales, shifts, Wf, bf, theta, n, noct);
}

// round 16
// speedup vs baseline: 1.0238x; 1.0238x over previous
#include <cuda_runtime.h>
#include <cuda_fp16.h>
#include <cstdint>

__device__ __forceinline__ float cos_fast(float x) {
    float y;
    asm("cos.approx.ftz.f32 %0, %1;" : "=f"(y) : "f"(x));
    return y;
}
// One MUFU instruction -> two tanhs (sm_75+)
__device__ __forceinline__ __half2 tanh_h2(__half2 x) {
    __half2 y;
    asm("tanh.approx.f16x2 %0, %1;"
        : "=r"(*reinterpret_cast<uint32_t*>(&y))
        : "r"(*reinterpret_cast<const uint32_t*>(&x)));
    return y;
}

#define N_LAYERS 5
#define Q_DEPTH  2

// fp32 coef smem: [0] wf0' [1] wf1' [2] bf'+K0 [3] K1 [4] K2 [5] K3-K4 [6] K4
// half2 coef smem (per layer l): [l*3+0]=(w00,w10) [l*3+1]=(w01,w11) [l*3+2]=(b0,b1)
#define NF32 7
#define NH2  (N_LAYERS * 3)

__device__ __forceinline__ void build_coefs(
    float* sf, __half2* sh,
    const float* __restrict__ Ws, const float* __restrict__ bs,
    const float* __restrict__ scales, const float* __restrict__ shifts,
    const float* __restrict__ Wf, const float* __restrict__ bf,
    const float* __restrict__ theta)
{
    // ---- fold scale/shift of layer l-1 into layer l (fp32), emit half2 ----
    float W[N_LAYERS][4], B[N_LAYERS][2];
    W[0][0] = Ws[0]; W[0][1] = Ws[1]; W[0][2] = Ws[2]; W[0][3] = Ws[3];
    B[0][0] = bs[0]; B[0][1] = bs[1];
#pragma unroll
    for (int l = 1; l < N_LAYERS; ++l) {
        float sc0 = scales[(l-1)*2+0], sc1 = scales[(l-1)*2+1];
        float sh0 = shifts[(l-1)*2+0], sh1 = shifts[(l-1)*2+1];
        float w00 = Ws[l*4+0], w01 = Ws[l*4+1], w10 = Ws[l*4+2], w11 = Ws[l*4+3];
        W[l][0] = w00 * sc0;
        W[l][1] = w01 * sc1;
        W[l][2] = w10 * sc0;
        W[l][3] = w11 * sc1;
        B[l][0] = fmaf(w00, sh0, fmaf(w01, sh1, bs[l*2+0]));
        B[l][1] = fmaf(w10, sh0, fmaf(w11, sh1, bs[l*2+1]));
    }
#pragma unroll
    for (int l = 0; l < N_LAYERS; ++l) {
        sh[l*3+0] = __floats2half2_rn(W[l][0], W[l][2]);   // (w00, w10)
        sh[l*3+1] = __floats2half2_rn(W[l][1], W[l][3]);   // (w01, w11)
        sh[l*3+2] = __floats2half2_rn(B[l][0], B[l][1]);   // (b0,  b1)
    }
    float lsc0 = scales[(N_LAYERS-1)*2+0], lsc1 = scales[(N_LAYERS-1)*2+1];
    float lsh0 = shifts[(N_LAYERS-1)*2+0], lsh1 = shifts[(N_LAYERS-1)*2+1];
    sf[0] = Wf[0] * lsc0;
    sf[1] = Wf[1] * lsc1;
    float bfp = fmaf(Wf[0], lsh0, fmaf(Wf[1], lsh1, bf[0]));

    // ---- U = prod_d [ CZ * (RY1 (x) RY0) ], real 4x4; rows 0 and 3 ----
    float U[4][4];
#pragma unroll
    for (int i = 0; i < 4; ++i)
#pragma unroll
        for (int j = 0; j < 4; ++j)
            U[i][j] = (i == j) ? 1.0f : 0.0f;

#pragma unroll
    for (int d = 0; d < Q_DEPTH; ++d) {
        float a0 = theta[d*2+0] * 0.5f;
        float a1 = theta[d*2+1] * 0.5f;
        float s0, c0, s1, c1;
        __sincosf(a0, &s0, &c0);
        __sincosf(a1, &s1, &c1);
        float ry0[2][2] = {{c0, -s0}, {s0, c0}};
        float ry1[2][2] = {{c1, -s1}, {s1, c1}};
        float M[4][4];
#pragma unroll
        for (int i = 0; i < 4; ++i)
#pragma unroll
            for (int j = 0; j < 4; ++j) {
                float acc = 0.0f;
#pragma unroll
                for (int k = 0; k < 4; ++k)
                    acc = fmaf(ry1[i>>1][k>>1] * ry0[i&1][k&1], U[k][j], acc);
                M[i][j] = acc;
            }
#pragma unroll
        for (int i = 0; i < 4; ++i)
#pragma unroll
            for (int j = 0; j < 4; ++j)
                U[i][j] = (i == 3) ? -M[i][j] : M[i][j];   // CZ flips |11> row
    }

    // q = K0 + K1 cos x0 + K2 cos x1 + K3 cos x0 cos x1 + K4 sin x0 sin x1
    float a = U[0][0]*U[0][0], b = U[0][1]*U[0][1], c = U[0][2]*U[0][2], dd = U[0][3]*U[0][3];
    float e = U[3][0]*U[3][0], f = U[3][1]*U[3][1], g = U[3][2]*U[3][2], h = U[3][3]*U[3][3];
    float cross0 = 2.0f * (U[0][1]*U[0][2] - U[0][0]*U[0][3]);
    float cross3 = 2.0f * (U[3][1]*U[3][2] - U[3][0]*U[3][3]);
    float K0 = 0.5f * ((a + b + c + dd) - (e + f + g + h));
    float K1 = 0.5f * ((a - b + c - dd) - (e - f + g - h));
    float K2 = 0.5f * ((a + b - c - dd) - (e + f - g - h));
    float K3 = 0.5f * ((a - b - c + dd) - (e - f - g + h));
    float K4 = 0.5f * (cross0 - cross3);
    sf[2] = bfp + K0;
    sf[3] = K1;
    sf[4] = K2;
    sf[5] = K3 - K4;     // coefficient of C0*C1 after product-to-sum
    sf[6] = K4;          // coefficient of cos(x0 - x1)
}

__global__ __launch_bounds__(256, 6)
void fraud_hybrid_fused(
    const float4* __restrict__ x4,    // [N/2] of (x0,x1) pairs
    float2*       __restrict__ out2,  // [N/2]
    const float*  __restrict__ x_raw,
    float*        __restrict__ out_raw,
    const float*  __restrict__ Ws, const float* __restrict__ bs,
    const float*  __restrict__ scales, const float* __restrict__ shifts,
    const float*  __restrict__ Wf, const float* __restrict__ bf,
    const float*  __restrict__ theta,
    int n, int nvec)
{
    __shared__ float   sf[NF32 + 1];
    __shared__ __half2 sh[NH2];
    if (threadIdx.x == 0)
        build_coefs(sf, sh, Ws, bs, scales, shifts, Wf, bf, theta);
    __syncthreads();

    // hoist constants to registers
    __half2 wc0[N_LAYERS], wc1[N_LAYERS], bb[N_LAYERS];
#pragma unroll
    for (int l = 0; l < N_LAYERS; ++l) {
        wc0[l] = sh[l*3+0];
        wc1[l] = sh[l*3+1];
        bb[l]  = sh[l*3+2];
    }
    const float wf0 = sf[0], wf1 = sf[1], bfK = sf[2];
    const float K1 = sf[3], K2 = sf[4], K34 = sf[5], K4 = sf[6];

    // quantum head: 3 cos (MUFU) + 5 FMA, all fp32
    auto qhead = [&](float x0, float x1) -> float {
        float C0 = cos_fast(x0);
        float C1 = cos_fast(x1);
        float CD = cos_fast(x0 - x1);       // sin x0 sin x1 = CD - C0*C1
        float cc = C0 * C1;
        return fmaf(K1, C0, fmaf(K2, C1, fmaf(K34, cc, K4 * CD)));
    };

    // backbone: fully fp16 — per layer 2 HFMA2 + 1 tanh.approx.f16x2
    auto backbone = [&](float x0, float x1) -> float {
        __half2 h = __floats2half2_rn(x0, x1);
#pragma unroll
        for (int l = 0; l < N_LAYERS; ++l) {
            __half2 hlo = __low2half2(h);    // (h0, h0)
            __half2 hhi = __high2half2(h);   // (h1, h1)
            __half2 z = __hfma2(hlo, wc0[l], __hfma2(hhi, wc1[l], bb[l]));
            h = tanh_h2(z);
        }
        float2 t = __half22float2(h);
        return fmaf(wf0, t.x, fmaf(wf1, t.y, bfK));
    };

    const int tid = blockIdx.x * blockDim.x + threadIdx.x;
    const int stride = gridDim.x * blockDim.x;

    // Persistent grid-stride; ONE LDG.128 per iteration (MLP_p1 = 1).
    // Each float4 = two (x0,x1) elements -> one float2 store.
    for (int i = tid; i < nvec; i += stride) {
        float4 a = __ldg(&x4[i]);
        float r0 = backbone(a.x, a.y) + qhead(a.x, a.y);
        float r1 = backbone(a.z, a.w) + qhead(a.z, a.w);
        out2[i] = make_float2(r0, r1);
    }

    // tail (n odd) — defensive; N = 4M is even
    if (tid == 0 && (n & 1)) {
        int idx = n - 1;
        float x0 = x_raw[2*idx], x1 = x_raw[2*idx+1];
        out_raw[idx] = backbone(x0, x1) + qhead(x0, x1);
    }
}

extern "C" void kernel_launch(void* const* d_in, const int* in_sizes, int n_in,
                              void* d_out, int out_size) {
    const float* x      = (const float*)d_in[0];  // [N,2]
    const float* Ws     = (const float*)d_in[1];  // [5,2,2]
    const float* bs     = (const float*)d_in[2];  // [5,2]
    const float* scales = (const float*)d_in[3];  // [5,2]
    const float* shifts = (const float*)d_in[4];  // [5,2]
    const float* Wf     = (const float*)d_in[5];  // [1,2]
    const float* bf     = (const float*)d_in[6];  // [1]
    const float* theta  = (const float*)d_in[7];  // [2,2]

    const int n = out_size;
    const int nvec = n >> 1;              // float4 tiles (2 elements each)

    const int threads = 256;
    int blocks = 148 * 6;                 // persistent: one full resident wave
    int max_blocks = (nvec + threads - 1) / threads;
    if (blocks > max_blocks) blocks = max_blocks;
    if (blocks < 1) blocks = 1;

    fraud_hybrid_fused<<<blocks, threads>>>(
        (const float4*)x, (float2*)d_out, x, (float*)d_out,
        Ws, bs, scales, shifts, Wf, bf, theta, n, nvec);
}